// round 5
// baseline (speedup 1.0000x reference)
#include <cuda_runtime.h>
#include <cstdint>

#define D_IN 64
#define D_EDGE 16
#define H 16
#define MAXN 102400
#define MAXE 3276800

// ---------------- static device scratch ----------------
__device__ float g_xm[MAXN * H + 64];    // x @ W_msg1[:64]
__device__ float g_sk1[MAXN * H + 64];   // x @ W_skip1 + b_skip1
__device__ float g_hm[MAXN * H + 64];    // h1 @ W_msg2[:16]
__device__ float g_agg2[MAXN * H + 64];  // conv2 partial (edge-const + skip2)
__device__ int   g_cur[MAXN];            // histogram -> local-excl prefix -> cursor
__device__ int   g_bsum[512];            // scan block sums (exclusive)
__device__ int2  g_se[MAXE];             // dst-sorted (src, eid)

// row bounds for node n, derived from post-scatter cursors:
//   end(n)   = g_bsum[n>>9] + g_cur[n]      (g_cur[n] = local_excl + deg after scatter)
//   start(n) = end(n-1), start(0) = 0
__device__ __forceinline__ int row_end(int n) {
    return g_bsum[n >> 9] + g_cur[n];
}

// ---------------------------------------------------------------------------
// Pass A: per node: xm = x @ Wm1[:64], sk1 = x @ Wsk1 + b_sk1
// ---------------------------------------------------------------------------
__global__ void pass_a(const float* __restrict__ x,
                       const float* __restrict__ Wm1,
                       const float* __restrict__ Wsk1,
                       const float* __restrict__ bsk1,
                       int N) {
    __shared__ float sWm[D_IN * H];
    __shared__ float sWs[D_IN * H];
    __shared__ float sb[H];
    __shared__ float sx[16 * D_IN];
    int tid = threadIdx.x;
    for (int i = tid; i < D_IN * H; i += 256) { sWm[i] = Wm1[i]; sWs[i] = Wsk1[i]; }
    if (tid < H) sb[tid] = bsk1[tid];
    int nbase = blockIdx.x * 16;
    for (int i = tid; i < 16 * D_IN; i += 256) {
        int n = nbase + (i >> 6);
        sx[i] = (n < N) ? x[(size_t)n * D_IN + (i & 63)] : 0.f;
    }
    __syncthreads();
    int ln = tid >> 4, j = tid & 15;
    int n = nbase + ln;
    if (n >= N) return;
    const float* xr = &sx[ln * D_IN];
    float a = 0.f, s = sb[j];
#pragma unroll
    for (int k = 0; k < D_IN; k++) {
        float xv = xr[k];
        a = fmaf(xv, sWm[k * H + j], a);
        s = fmaf(xv, sWs[k * H + j], s);
    }
    int o = n * H + j;
    g_xm[o] = a;
    g_sk1[o] = s;
}

// ---------------------------------------------------------------------------
// Counting sort by dst
// ---------------------------------------------------------------------------
__global__ void k_hist(const int* __restrict__ ei, int E) {
    int e = blockIdx.x * 256 + threadIdx.x;
    if (e < E) atomicAdd(&g_cur[ei[(size_t)E + e]], 1);
}
__global__ void k_scan1(int N) {
    __shared__ int s[2][512];
    int t = threadIdx.x;
    int i = blockIdx.x * 512 + t;
    int v = (i < N) ? g_cur[i] : 0;
    s[0][t] = v;
    __syncthreads();
    int a = 0;
#pragma unroll
    for (int off = 1; off < 512; off <<= 1) {
        int sr = a; a ^= 1;
        s[a][t] = s[sr][t] + ((t >= off) ? s[sr][t - off] : 0);
        __syncthreads();
    }
    int incl = s[a][t];
    if (i < N) g_cur[i] = incl - v;  // local exclusive
    if (t == 511) g_bsum[blockIdx.x] = incl;
}
__global__ void k_scan2(int nsb) {
    __shared__ int s[2][512];
    int t = threadIdx.x;
    int v = (t < nsb) ? g_bsum[t] : 0;
    s[0][t] = v;
    __syncthreads();
    int a = 0;
#pragma unroll
    for (int off = 1; off < 512; off <<= 1) {
        int sr = a; a ^= 1;
        s[a][t] = s[sr][t] + ((t >= off) ? s[sr][t - off] : 0);
        __syncthreads();
    }
    if (t < nsb) g_bsum[t] = s[a][t] - v;  // exclusive
}
__global__ void k_scatter(const int* __restrict__ ei, int E) {
    int e = blockIdx.x * 256 + threadIdx.x;
    if (e >= E) return;
    int s = ei[e];
    int d = ei[(size_t)E + e];
    int p = g_bsum[d >> 9] + atomicAdd(&g_cur[d], 1);
    g_se[p] = make_int2(s, e);
}

// ---------------------------------------------------------------------------
// Pass BC (fused conv1 + inter-layer): one warp per node, 4-wide pipelined
// gather. lanes: eslot = lane>>2 (8 parallel edges), c = lane&3 (f4 quarter)
// ---------------------------------------------------------------------------
__global__ void pass_bc(const float* __restrict__ ea,
                        const float* __restrict__ Wm1,
                        const float* __restrict__ b1,
                        const float* __restrict__ Wm2,
                        const float* __restrict__ b2,
                        const float* __restrict__ Wsk2,
                        const float* __restrict__ bsk2,
                        int N) {
    __shared__ float sW1e[H * H];   // Wm1 rows 64..79
    __shared__ float sW2e[H * H];   // Wm2 rows 16..31
    __shared__ float sWm2[H * H];   // Wm2 rows 0..15
    __shared__ float sWs2[H * H];   // Wsk2
    __shared__ float sb1[H], sb2[H], sbs2[H];
    __shared__ float sS[8][48];     // per warp: Sx[0:16) Se[16:32) h1[32:48)
    int tid = threadIdx.x;
    sW1e[tid] = Wm1[D_IN * H + tid];
    sWm2[tid] = Wm2[tid];
    sW2e[tid] = Wm2[H * H + tid];
    sWs2[tid] = Wsk2[tid];
    if (tid < H) { sb1[tid] = b1[tid]; sb2[tid] = b2[tid]; sbs2[tid] = bsk2[tid]; }
    __syncthreads();

    int w = tid >> 5, lane = tid & 31;
    int n = blockIdx.x * 8 + w;
    if (n >= N) return;
    int r1 = row_end(n);
    int r0 = (n == 0) ? 0 : row_end(n - 1);
    int eslot = lane >> 2, c = lane & 3;

    float ax0 = 0.f, ax1 = 0.f, ax2 = 0.f, ax3 = 0.f;
    float ae0 = 0.f, ae1 = 0.f, ae2 = 0.f, ae3 = 0.f;
    int p = r0 + eslot;
    // 4-wide software-pipelined main loop (independent gathers -> MLP 4)
    while (p + 24 < r1) {
        int2 s0 = g_se[p];
        int2 s1 = g_se[p + 8];
        int2 s2 = g_se[p + 16];
        int2 s3 = g_se[p + 24];
        float4 e0 = __ldg((const float4*)ea + (size_t)s0.y * 4 + c);
        float4 e1 = __ldg((const float4*)ea + (size_t)s1.y * 4 + c);
        float4 e2 = __ldg((const float4*)ea + (size_t)s2.y * 4 + c);
        float4 e3 = __ldg((const float4*)ea + (size_t)s3.y * 4 + c);
        float4 x0 = __ldg((const float4*)g_xm + (size_t)s0.x * 4 + c);
        float4 x1 = __ldg((const float4*)g_xm + (size_t)s1.x * 4 + c);
        float4 x2 = __ldg((const float4*)g_xm + (size_t)s2.x * 4 + c);
        float4 x3 = __ldg((const float4*)g_xm + (size_t)s3.x * 4 + c);
        ax0 += (x0.x + x1.x) + (x2.x + x3.x);
        ax1 += (x0.y + x1.y) + (x2.y + x3.y);
        ax2 += (x0.z + x1.z) + (x2.z + x3.z);
        ax3 += (x0.w + x1.w) + (x2.w + x3.w);
        ae0 += (e0.x + e1.x) + (e2.x + e3.x);
        ae1 += (e0.y + e1.y) + (e2.y + e3.y);
        ae2 += (e0.z + e1.z) + (e2.z + e3.z);
        ae3 += (e0.w + e1.w) + (e2.w + e3.w);
        p += 32;
    }
    while (p < r1) {
        int2 se = g_se[p];
        float4 e4 = __ldg((const float4*)ea + (size_t)se.y * 4 + c);
        float4 x4 = __ldg((const float4*)g_xm + (size_t)se.x * 4 + c);
        ax0 += x4.x; ax1 += x4.y; ax2 += x4.z; ax3 += x4.w;
        ae0 += e4.x; ae1 += e4.y; ae2 += e4.z; ae3 += e4.w;
        p += 8;
    }
#pragma unroll
    for (int off = 4; off < 32; off <<= 1) {
        ax0 += __shfl_xor_sync(0xffffffffu, ax0, off);
        ax1 += __shfl_xor_sync(0xffffffffu, ax1, off);
        ax2 += __shfl_xor_sync(0xffffffffu, ax2, off);
        ax3 += __shfl_xor_sync(0xffffffffu, ax3, off);
        ae0 += __shfl_xor_sync(0xffffffffu, ae0, off);
        ae1 += __shfl_xor_sync(0xffffffffu, ae1, off);
        ae2 += __shfl_xor_sync(0xffffffffu, ae2, off);
        ae3 += __shfl_xor_sync(0xffffffffu, ae3, off);
    }
    if (eslot == 0) {
        float* S = sS[w];
        S[c * 4 + 0] = ax0; S[c * 4 + 1] = ax1; S[c * 4 + 2] = ax2; S[c * 4 + 3] = ax3;
        S[16 + c * 4 + 0] = ae0; S[16 + c * 4 + 1] = ae1; S[16 + c * 4 + 2] = ae2; S[16 + c * 4 + 3] = ae3;
    }
    __syncwarp();

    float deg = (float)(r1 - r0);
    if (lane < 16) {
        int j = lane;
        float a = sS[w][j] + deg * sb1[j] + g_sk1[n * H + j];
#pragma unroll
        for (int k = 0; k < H; k++) a = fmaf(sS[w][16 + k], sW1e[k * H + j], a);
        sS[w][32 + j] = fmaxf(a, 0.f);
    }
    __syncwarp();
    if (lane < 16) {
        int j = lane;
        float hm = 0.f;
        float a2 = deg * sb2[j] + sbs2[j];
#pragma unroll
        for (int k = 0; k < H; k++) {
            float hk = sS[w][32 + k];
            hm = fmaf(hk, sWm2[k * H + j], hm);
            a2 = fmaf(hk, sWs2[k * H + j], a2);
            a2 = fmaf(sS[w][16 + k], sW2e[k * H + j], a2);
        }
        g_hm[n * H + j] = hm;
        g_agg2[n * H + j] = a2;
    }
}

// ---------------------------------------------------------------------------
// Pass DE (fused conv2-aggregate + lin3): one warp per node, pipelined gather
// ---------------------------------------------------------------------------
__global__ void pass_de(const float* __restrict__ Wl3,
                        const float* __restrict__ bl3,
                        float* __restrict__ out, int N) {
    __shared__ float sW[H * D_IN];
    __shared__ float sb[D_IN];
    __shared__ float sH[8][20];
    int tid = threadIdx.x;
    for (int i = tid; i < H * D_IN; i += 256) sW[i] = Wl3[i];
    if (tid < D_IN) sb[tid] = bl3[tid];
    __syncthreads();

    int w = tid >> 5, lane = tid & 31;
    int n = blockIdx.x * 8 + w;
    if (n >= N) return;
    int r1 = row_end(n);
    int r0 = (n == 0) ? 0 : row_end(n - 1);
    int eslot = lane >> 2, c = lane & 3;

    float a0 = 0.f, a1 = 0.f, a2 = 0.f, a3 = 0.f;
    int p = r0 + eslot;
    while (p + 24 < r1) {
        int s0 = g_se[p].x;
        int s1 = g_se[p + 8].x;
        int s2 = g_se[p + 16].x;
        int s3 = g_se[p + 24].x;
        float4 h0 = __ldg((const float4*)g_hm + (size_t)s0 * 4 + c);
        float4 h1 = __ldg((const float4*)g_hm + (size_t)s1 * 4 + c);
        float4 h2 = __ldg((const float4*)g_hm + (size_t)s2 * 4 + c);
        float4 h3 = __ldg((const float4*)g_hm + (size_t)s3 * 4 + c);
        a0 += (h0.x + h1.x) + (h2.x + h3.x);
        a1 += (h0.y + h1.y) + (h2.y + h3.y);
        a2 += (h0.z + h1.z) + (h2.z + h3.z);
        a3 += (h0.w + h1.w) + (h2.w + h3.w);
        p += 32;
    }
    while (p < r1) {
        int src = g_se[p].x;
        float4 h4 = __ldg((const float4*)g_hm + (size_t)src * 4 + c);
        a0 += h4.x; a1 += h4.y; a2 += h4.z; a3 += h4.w;
        p += 8;
    }
#pragma unroll
    for (int off = 4; off < 32; off <<= 1) {
        a0 += __shfl_xor_sync(0xffffffffu, a0, off);
        a1 += __shfl_xor_sync(0xffffffffu, a1, off);
        a2 += __shfl_xor_sync(0xffffffffu, a2, off);
        a3 += __shfl_xor_sync(0xffffffffu, a3, off);
    }
    if (eslot == 0) {
        int b = c * 4;
        const float* ag = &g_agg2[n * H];
        sH[w][b + 0] = a0 + ag[b + 0];
        sH[w][b + 1] = a1 + ag[b + 1];
        sH[w][b + 2] = a2 + ag[b + 2];
        sH[w][b + 3] = a3 + ag[b + 3];
    }
    __syncwarp();

    float acc0 = sb[lane], acc1 = sb[lane + 32];
#pragma unroll
    for (int k = 0; k < H; k++) {
        float hk = sH[w][k];
        acc0 = fmaf(hk, sW[k * D_IN + lane], acc0);
        acc1 = fmaf(hk, sW[k * D_IN + lane + 32], acc1);
    }
    out[(size_t)n * D_IN + lane] = acc0;
    out[(size_t)n * D_IN + lane + 32] = acc1;
}

// ---------------------------------------------------------------------------
extern "C" void kernel_launch(void* const* d_in, const int* in_sizes, int n_in,
                              void* d_out, int out_size) {
    const float* x    = (const float*)d_in[0];
    const int*   ei   = (const int*)d_in[1];
    const float* ea   = (const float*)d_in[2];
    const float* Wm1  = (const float*)d_in[3];
    const float* bm1  = (const float*)d_in[4];
    const float* Wsk1 = (const float*)d_in[5];
    const float* bsk1 = (const float*)d_in[6];
    const float* Wm2  = (const float*)d_in[7];
    const float* bm2  = (const float*)d_in[8];
    const float* Wsk2 = (const float*)d_in[9];
    const float* bsk2 = (const float*)d_in[10];
    const float* Wl3  = (const float*)d_in[11];
    const float* bl3  = (const float*)d_in[12];
    float* out = (float*)d_out;

    int N = in_sizes[0] / D_IN;
    int E = in_sizes[1] / 2;

    int ebl = (E + 255) / 256;
    int nsb = (N + 511) / 512;

    void* cur_ptr = nullptr;
    cudaGetSymbolAddress(&cur_ptr, g_cur);
    cudaMemsetAsync(cur_ptr, 0, (size_t)N * sizeof(int), 0);

    pass_a<<<(N + 15) / 16, 256>>>(x, Wm1, Wsk1, bsk1, N);
    k_hist<<<ebl, 256>>>(ei, E);
    k_scan1<<<nsb, 512>>>(N);
    k_scan2<<<1, 512>>>(nsb);
    k_scatter<<<ebl, 256>>>(ei, E);
    pass_bc<<<(N + 7) / 8, 256>>>(ea, Wm1, bm1, Wm2, bm2, Wsk2, bsk2, N);
    pass_de<<<(N + 7) / 8, 256>>>(Wl3, bl3, out, N);
}

// round 6
// speedup vs baseline: 1.0131x; 1.0131x over previous
#include <cuda_runtime.h>
#include <cstdint>

#define D_IN 64
#define D_EDGE 16
#define H 16
#define MAXN 102400
#define MAXE 3276800

// ---------------- static device scratch ----------------
__device__ float g_xm[MAXN * H + 64];    // x @ W_msg1[:64]
__device__ float g_sk1[MAXN * H + 64];   // x @ W_skip1 + b_skip1
__device__ float g_hm[MAXN * H + 64];    // h1 @ W_msg2[:16]
__device__ float g_agg2[MAXN * H + 64];  // conv2 partial (edge-const + skip2)
__device__ int   g_cur[MAXN];            // histogram -> local-excl prefix -> cursor
__device__ int   g_bsum[512];            // scan block sums (exclusive)
__device__ int   g_done;                 // scan completion counter
__device__ int2  g_se[MAXE];             // dst-sorted (src, eid)

// row bounds for node n, derived from post-scatter cursors:
//   end(n)   = g_bsum[n>>9] + g_cur[n]   (g_cur[n] = local_excl + deg after scatter)
//   start(n) = end(n-1), start(0) = 0
__device__ __forceinline__ int row_end(int n) {
    return g_bsum[n >> 9] + g_cur[n];
}

#define HIST_EDGES 4096

// ---------------------------------------------------------------------------
// Kernel 1: fused pass_a (node MLP) + dst histogram.
// Blocks [0, nbA): per node xm = x@Wm1[:64], sk1 = x@Wsk1 + b.
// Blocks [nbA, nbA+ebl): histogram a chunk of HIST_EDGES edges.
// ---------------------------------------------------------------------------
__global__ void pass_a_hist(const float* __restrict__ x,
                            const float* __restrict__ Wm1,
                            const float* __restrict__ Wsk1,
                            const float* __restrict__ bsk1,
                            const int* __restrict__ ei,
                            int N, int E, int nbA) {
    int tid = threadIdx.x;
    if ((int)blockIdx.x >= nbA) {
        int base = (blockIdx.x - nbA) * HIST_EDGES;
        int lim = min(base + HIST_EDGES, E);
        for (int e = base + tid; e < lim; e += 256)
            atomicAdd(&g_cur[ei[(size_t)E + e]], 1);
        return;
    }
    __shared__ float sWm[D_IN * H];
    __shared__ float sWs[D_IN * H];
    __shared__ float sb[H];
    __shared__ float sx[16 * D_IN];
    for (int i = tid; i < D_IN * H; i += 256) { sWm[i] = Wm1[i]; sWs[i] = Wsk1[i]; }
    if (tid < H) sb[tid] = bsk1[tid];
    int nbase = blockIdx.x * 16;
    for (int i = tid; i < 16 * D_IN; i += 256) {
        int n = nbase + (i >> 6);
        sx[i] = (n < N) ? x[(size_t)n * D_IN + (i & 63)] : 0.f;
    }
    __syncthreads();
    int ln = tid >> 4, j = tid & 15;
    int n = nbase + ln;
    if (n >= N) return;
    const float* xr = &sx[ln * D_IN];
    float a = 0.f, s = sb[j];
#pragma unroll
    for (int k = 0; k < D_IN; k++) {
        float xv = xr[k];
        a = fmaf(xv, sWm[k * H + j], a);
        s = fmaf(xv, sWs[k * H + j], s);
    }
    int o = n * H + j;
    g_xm[o] = a;
    g_sk1[o] = s;
}

// ---------------------------------------------------------------------------
// Kernel 2: fused two-level scan. Per-block scan of 512 counts -> local
// exclusive in g_cur + block sum in g_bsum; the LAST block to finish then
// exclusive-scans g_bsum in place.
// ---------------------------------------------------------------------------
__global__ void k_scan(int N) {
    __shared__ int s[2][512];
    __shared__ int s_last;
    int t = threadIdx.x;
    int i = blockIdx.x * 512 + t;
    int v = (i < N) ? g_cur[i] : 0;
    s[0][t] = v;
    __syncthreads();
    int a = 0;
#pragma unroll
    for (int off = 1; off < 512; off <<= 1) {
        int sr = a; a ^= 1;
        s[a][t] = s[sr][t] + ((t >= off) ? s[sr][t - off] : 0);
        __syncthreads();
    }
    int incl = s[a][t];
    if (i < N) g_cur[i] = incl - v;  // local exclusive
    if (t == 511) g_bsum[blockIdx.x] = incl;
    __threadfence();
    __syncthreads();
    if (t == 0) s_last = (atomicAdd(&g_done, 1) == (int)gridDim.x - 1);
    __syncthreads();
    if (!s_last) return;
    // final block: exclusive scan of block sums
    int nsb = gridDim.x;
    int bv = (t < nsb) ? g_bsum[t] : 0;
    s[0][t] = bv;
    __syncthreads();
    a = 0;
#pragma unroll
    for (int off = 1; off < 512; off <<= 1) {
        int sr = a; a ^= 1;
        s[a][t] = s[sr][t] + ((t >= off) ? s[sr][t - off] : 0);
        __syncthreads();
    }
    if (t < nsb) g_bsum[t] = s[a][t] - bv;
}

// ---------------------------------------------------------------------------
// Kernel 3: scatter edges to dst-sorted order
// ---------------------------------------------------------------------------
__global__ void k_scatter(const int* __restrict__ ei, int E) {
    int e = blockIdx.x * 256 + threadIdx.x;
    if (e >= E) return;
    int s = ei[e];
    int d = ei[(size_t)E + e];
    int p = g_bsum[d >> 9] + atomicAdd(&g_cur[d], 1);
    g_se[p] = make_int2(s, e);
}

// ---------------------------------------------------------------------------
// Kernel 4: Pass BC (fused conv1 + inter-layer): one warp per node.
// lanes: eslot = lane>>2 (8 parallel edges), c = lane&3 (f4 quarter)
// ---------------------------------------------------------------------------
__global__ void pass_bc(const float* __restrict__ ea,
                        const float* __restrict__ Wm1,
                        const float* __restrict__ b1,
                        const float* __restrict__ Wm2,
                        const float* __restrict__ b2,
                        const float* __restrict__ Wsk2,
                        const float* __restrict__ bsk2,
                        int N) {
    __shared__ float sW1e[H * H];   // Wm1 rows 64..79
    __shared__ float sW2e[H * H];   // Wm2 rows 16..31
    __shared__ float sWm2[H * H];   // Wm2 rows 0..15
    __shared__ float sWs2[H * H];   // Wsk2
    __shared__ float sb1[H], sb2[H], sbs2[H];
    __shared__ float sS[8][48];     // per warp: Sx[0:16) Se[16:32) h1[32:48)
    int tid = threadIdx.x;
    sW1e[tid] = Wm1[D_IN * H + tid];
    sWm2[tid] = Wm2[tid];
    sW2e[tid] = Wm2[H * H + tid];
    sWs2[tid] = Wsk2[tid];
    if (tid < H) { sb1[tid] = b1[tid]; sb2[tid] = b2[tid]; sbs2[tid] = bsk2[tid]; }
    __syncthreads();

    int w = tid >> 5, lane = tid & 31;
    int n = blockIdx.x * 8 + w;
    if (n >= N) return;
    int r1 = row_end(n);
    int r0 = (n == 0) ? 0 : row_end(n - 1);
    int eslot = lane >> 2, c = lane & 3;

    float ax0 = 0.f, ax1 = 0.f, ax2 = 0.f, ax3 = 0.f;
    float ae0 = 0.f, ae1 = 0.f, ae2 = 0.f, ae3 = 0.f;
    int p = r0 + eslot;
    while (p + 24 < r1) {
        int2 s0 = g_se[p];
        int2 s1 = g_se[p + 8];
        int2 s2 = g_se[p + 16];
        int2 s3 = g_se[p + 24];
        float4 e0 = __ldg((const float4*)ea + (size_t)s0.y * 4 + c);
        float4 e1 = __ldg((const float4*)ea + (size_t)s1.y * 4 + c);
        float4 e2 = __ldg((const float4*)ea + (size_t)s2.y * 4 + c);
        float4 e3 = __ldg((const float4*)ea + (size_t)s3.y * 4 + c);
        float4 x0 = __ldg((const float4*)g_xm + (size_t)s0.x * 4 + c);
        float4 x1 = __ldg((const float4*)g_xm + (size_t)s1.x * 4 + c);
        float4 x2 = __ldg((const float4*)g_xm + (size_t)s2.x * 4 + c);
        float4 x3 = __ldg((const float4*)g_xm + (size_t)s3.x * 4 + c);
        ax0 += (x0.x + x1.x) + (x2.x + x3.x);
        ax1 += (x0.y + x1.y) + (x2.y + x3.y);
        ax2 += (x0.z + x1.z) + (x2.z + x3.z);
        ax3 += (x0.w + x1.w) + (x2.w + x3.w);
        ae0 += (e0.x + e1.x) + (e2.x + e3.x);
        ae1 += (e0.y + e1.y) + (e2.y + e3.y);
        ae2 += (e0.z + e1.z) + (e2.z + e3.z);
        ae3 += (e0.w + e1.w) + (e2.w + e3.w);
        p += 32;
    }
    while (p < r1) {
        int2 se = g_se[p];
        float4 e4 = __ldg((const float4*)ea + (size_t)se.y * 4 + c);
        float4 x4 = __ldg((const float4*)g_xm + (size_t)se.x * 4 + c);
        ax0 += x4.x; ax1 += x4.y; ax2 += x4.z; ax3 += x4.w;
        ae0 += e4.x; ae1 += e4.y; ae2 += e4.z; ae3 += e4.w;
        p += 8;
    }
#pragma unroll
    for (int off = 4; off < 32; off <<= 1) {
        ax0 += __shfl_xor_sync(0xffffffffu, ax0, off);
        ax1 += __shfl_xor_sync(0xffffffffu, ax1, off);
        ax2 += __shfl_xor_sync(0xffffffffu, ax2, off);
        ax3 += __shfl_xor_sync(0xffffffffu, ax3, off);
        ae0 += __shfl_xor_sync(0xffffffffu, ae0, off);
        ae1 += __shfl_xor_sync(0xffffffffu, ae1, off);
        ae2 += __shfl_xor_sync(0xffffffffu, ae2, off);
        ae3 += __shfl_xor_sync(0xffffffffu, ae3, off);
    }
    if (eslot == 0) {
        float* S = sS[w];
        S[c * 4 + 0] = ax0; S[c * 4 + 1] = ax1; S[c * 4 + 2] = ax2; S[c * 4 + 3] = ax3;
        S[16 + c * 4 + 0] = ae0; S[16 + c * 4 + 1] = ae1; S[16 + c * 4 + 2] = ae2; S[16 + c * 4 + 3] = ae3;
    }
    __syncwarp();

    float deg = (float)(r1 - r0);
    if (lane < 16) {
        int j = lane;
        float a = sS[w][j] + deg * sb1[j] + g_sk1[n * H + j];
#pragma unroll
        for (int k = 0; k < H; k++) a = fmaf(sS[w][16 + k], sW1e[k * H + j], a);
        sS[w][32 + j] = fmaxf(a, 0.f);
    }
    __syncwarp();
    if (lane < 16) {
        int j = lane;
        float hm = 0.f;
        float a2 = deg * sb2[j] + sbs2[j];
#pragma unroll
        for (int k = 0; k < H; k++) {
            float hk = sS[w][32 + k];
            hm = fmaf(hk, sWm2[k * H + j], hm);
            a2 = fmaf(hk, sWs2[k * H + j], a2);
            a2 = fmaf(sS[w][16 + k], sW2e[k * H + j], a2);
        }
        g_hm[n * H + j] = hm;
        g_agg2[n * H + j] = a2;
    }
}

// ---------------------------------------------------------------------------
// Kernel 5: Pass DE (fused conv2-aggregate + lin3): one warp per node.
// ---------------------------------------------------------------------------
__global__ void pass_de(const float* __restrict__ Wl3,
                        const float* __restrict__ bl3,
                        float* __restrict__ out, int N) {
    __shared__ float sW[H * D_IN];
    __shared__ float sb[D_IN];
    __shared__ float sH[8][20];
    int tid = threadIdx.x;
    for (int i = tid; i < H * D_IN; i += 256) sW[i] = Wl3[i];
    if (tid < D_IN) sb[tid] = bl3[tid];
    __syncthreads();

    int w = tid >> 5, lane = tid & 31;
    int n = blockIdx.x * 8 + w;
    if (n >= N) return;
    int r1 = row_end(n);
    int r0 = (n == 0) ? 0 : row_end(n - 1);
    int eslot = lane >> 2, c = lane & 3;

    float a0 = 0.f, a1 = 0.f, a2 = 0.f, a3 = 0.f;
    int p = r0 + eslot;
    while (p + 24 < r1) {
        int s0 = g_se[p].x;
        int s1 = g_se[p + 8].x;
        int s2 = g_se[p + 16].x;
        int s3 = g_se[p + 24].x;
        float4 h0 = __ldg((const float4*)g_hm + (size_t)s0 * 4 + c);
        float4 h1 = __ldg((const float4*)g_hm + (size_t)s1 * 4 + c);
        float4 h2 = __ldg((const float4*)g_hm + (size_t)s2 * 4 + c);
        float4 h3 = __ldg((const float4*)g_hm + (size_t)s3 * 4 + c);
        a0 += (h0.x + h1.x) + (h2.x + h3.x);
        a1 += (h0.y + h1.y) + (h2.y + h3.y);
        a2 += (h0.z + h1.z) + (h2.z + h3.z);
        a3 += (h0.w + h1.w) + (h2.w + h3.w);
        p += 32;
    }
    while (p < r1) {
        int src = g_se[p].x;
        float4 h4 = __ldg((const float4*)g_hm + (size_t)src * 4 + c);
        a0 += h4.x; a1 += h4.y; a2 += h4.z; a3 += h4.w;
        p += 8;
    }
#pragma unroll
    for (int off = 4; off < 32; off <<= 1) {
        a0 += __shfl_xor_sync(0xffffffffu, a0, off);
        a1 += __shfl_xor_sync(0xffffffffu, a1, off);
        a2 += __shfl_xor_sync(0xffffffffu, a2, off);
        a3 += __shfl_xor_sync(0xffffffffu, a3, off);
    }
    if (eslot == 0) {
        int b = c * 4;
        const float* ag = &g_agg2[n * H];
        sH[w][b + 0] = a0 + ag[b + 0];
        sH[w][b + 1] = a1 + ag[b + 1];
        sH[w][b + 2] = a2 + ag[b + 2];
        sH[w][b + 3] = a3 + ag[b + 3];
    }
    __syncwarp();

    float acc0 = sb[lane], acc1 = sb[lane + 32];
#pragma unroll
    for (int k = 0; k < H; k++) {
        float hk = sH[w][k];
        acc0 = fmaf(hk, sW[k * D_IN + lane], acc0);
        acc1 = fmaf(hk, sW[k * D_IN + lane + 32], acc1);
    }
    out[(size_t)n * D_IN + lane] = acc0;
    out[(size_t)n * D_IN + lane + 32] = acc1;
}

// ---------------------------------------------------------------------------
extern "C" void kernel_launch(void* const* d_in, const int* in_sizes, int n_in,
                              void* d_out, int out_size) {
    const float* x    = (const float*)d_in[0];
    const int*   ei   = (const int*)d_in[1];
    const float* ea   = (const float*)d_in[2];
    const float* Wm1  = (const float*)d_in[3];
    const float* bm1  = (const float*)d_in[4];
    const float* Wsk1 = (const float*)d_in[5];
    const float* bsk1 = (const float*)d_in[6];
    const float* Wm2  = (const float*)d_in[7];
    const float* bm2  = (const float*)d_in[8];
    const float* Wsk2 = (const float*)d_in[9];
    const float* bsk2 = (const float*)d_in[10];
    const float* Wl3  = (const float*)d_in[11];
    const float* bl3  = (const float*)d_in[12];
    float* out = (float*)d_out;

    int N = in_sizes[0] / D_IN;
    int E = in_sizes[1] / 2;

    int nbA = (N + 15) / 16;
    int ebl = (E + HIST_EDGES - 1) / HIST_EDGES;
    int nsb = (N + 511) / 512;

    void* cur_ptr = nullptr;
    void* done_ptr = nullptr;
    cudaGetSymbolAddress(&cur_ptr, g_cur);
    cudaGetSymbolAddress(&done_ptr, g_done);
    cudaMemsetAsync(cur_ptr, 0, (size_t)N * sizeof(int), 0);
    cudaMemsetAsync(done_ptr, 0, sizeof(int), 0);

    pass_a_hist<<<nbA + ebl, 256>>>(x, Wm1, Wsk1, bsk1, ei, N, E, nbA);
    k_scan<<<nsb, 512>>>(N);
    k_scatter<<<(E + 255) / 256, 256>>>(ei, E);
    pass_bc<<<(N + 7) / 8, 256>>>(ea, Wm1, bm1, Wm2, bm2, Wsk2, bsk2, N);
    pass_de<<<(N + 7) / 8, 256>>>(Wl3, bl3, out, N);
}

// round 7
// speedup vs baseline: 1.0314x; 1.0181x over previous
#include <cuda_runtime.h>
#include <cstdint>

#define D_IN 64
#define D_EDGE 16
#define H 16
#define MAXN 102400
#define MAXE 3276800

// ---------------- static device scratch ----------------
__device__ float g_xm[MAXN * H + 64];    // x @ W_msg1[:64]
__device__ float g_sk1[MAXN * H + 64];   // x @ W_skip1 + b_skip1
__device__ float g_hm[MAXN * H + 64];    // h1 @ W_msg2[:16]
__device__ float g_agg2[MAXN * H + 64];  // conv2 partial (edge-const + skip2)
__device__ int   g_cur[MAXN];            // histogram -> local-excl prefix -> cursor
__device__ int   g_bsum[512];            // scan block sums (exclusive)
__device__ int   g_done;                 // scan completion counter
__device__ int2  g_se[MAXE];             // dst-sorted (src, eid)

// row bounds: end(n) = g_bsum[n>>9] + g_cur[n]; start(n) = end(n-1); start(0)=0
__device__ __forceinline__ int row_end(int n) {
    return g_bsum[n >> 9] + g_cur[n];
}

#define HIST_EDGES 4096

// ---------------------------------------------------------------------------
// pass_a (runs on forked stream, overlaps hist/scan/scatter):
// per node: xm = x @ Wm1[:64], sk1 = x @ Wsk1 + b_sk1
// ---------------------------------------------------------------------------
__global__ void pass_a(const float* __restrict__ x,
                       const float* __restrict__ Wm1,
                       const float* __restrict__ Wsk1,
                       const float* __restrict__ bsk1,
                       int N) {
    __shared__ float sWm[D_IN * H];
    __shared__ float sWs[D_IN * H];
    __shared__ float sb[H];
    __shared__ float sx[16 * D_IN];
    int tid = threadIdx.x;
    for (int i = tid; i < D_IN * H; i += 256) { sWm[i] = Wm1[i]; sWs[i] = Wsk1[i]; }
    if (tid < H) sb[tid] = bsk1[tid];
    int nbase = blockIdx.x * 16;
    for (int i = tid; i < 16 * D_IN; i += 256) {
        int n = nbase + (i >> 6);
        sx[i] = (n < N) ? x[(size_t)n * D_IN + (i & 63)] : 0.f;
    }
    __syncthreads();
    int ln = tid >> 4, j = tid & 15;
    int n = nbase + ln;
    if (n >= N) return;
    const float* xr = &sx[ln * D_IN];
    float a = 0.f, s = sb[j];
#pragma unroll
    for (int k = 0; k < D_IN; k++) {
        float xv = xr[k];
        a = fmaf(xv, sWm[k * H + j], a);
        s = fmaf(xv, sWs[k * H + j], s);
    }
    int o = n * H + j;
    g_xm[o] = a;
    g_sk1[o] = s;
}

// ---------------------------------------------------------------------------
// k_hist: dst histogram (chunked)
// ---------------------------------------------------------------------------
__global__ void k_hist(const int* __restrict__ ei, int E) {
    int base = blockIdx.x * HIST_EDGES;
    int lim = min(base + HIST_EDGES, E);
    for (int e = base + threadIdx.x; e < lim; e += 256)
        atomicAdd(&g_cur[ei[(size_t)E + e]], 1);
}

// ---------------------------------------------------------------------------
// k_scan: fused two-level scan (last-block-done trick)
// ---------------------------------------------------------------------------
__global__ void k_scan(int N) {
    __shared__ int s[2][512];
    __shared__ int s_last;
    int t = threadIdx.x;
    int i = blockIdx.x * 512 + t;
    int v = (i < N) ? g_cur[i] : 0;
    s[0][t] = v;
    __syncthreads();
    int a = 0;
#pragma unroll
    for (int off = 1; off < 512; off <<= 1) {
        int sr = a; a ^= 1;
        s[a][t] = s[sr][t] + ((t >= off) ? s[sr][t - off] : 0);
        __syncthreads();
    }
    int incl = s[a][t];
    if (i < N) g_cur[i] = incl - v;  // local exclusive
    if (t == 511) g_bsum[blockIdx.x] = incl;
    __threadfence();
    __syncthreads();
    if (t == 0) s_last = (atomicAdd(&g_done, 1) == (int)gridDim.x - 1);
    __syncthreads();
    if (!s_last) return;
    int nsb = gridDim.x;
    int bv = (t < nsb) ? g_bsum[t] : 0;
    s[0][t] = bv;
    __syncthreads();
    a = 0;
#pragma unroll
    for (int off = 1; off < 512; off <<= 1) {
        int sr = a; a ^= 1;
        s[a][t] = s[sr][t] + ((t >= off) ? s[sr][t - off] : 0);
        __syncthreads();
    }
    if (t < nsb) g_bsum[t] = s[a][t] - bv;
}

// ---------------------------------------------------------------------------
// k_scatter: edges -> dst-sorted order
// ---------------------------------------------------------------------------
__global__ void k_scatter(const int* __restrict__ ei, int E) {
    int e = blockIdx.x * 256 + threadIdx.x;
    if (e >= E) return;
    int s = ei[e];
    int d = ei[(size_t)E + e];
    int p = g_bsum[d >> 9] + atomicAdd(&g_cur[d], 1);
    g_se[p] = make_int2(s, e);
}

// ---------------------------------------------------------------------------
// pass_bc (fused conv1 + inter-layer): one warp per node.
// lanes: eslot = lane>>2 (8 parallel edges), c = lane&3 (f4 quarter)
// ---------------------------------------------------------------------------
__global__ void __launch_bounds__(256, 6)
pass_bc(const float* __restrict__ ea,
        const float* __restrict__ Wm1,
        const float* __restrict__ b1,
        const float* __restrict__ Wm2,
        const float* __restrict__ b2,
        const float* __restrict__ Wsk2,
        const float* __restrict__ bsk2,
        int N) {
    __shared__ float sW1e[H * H];   // Wm1 rows 64..79
    __shared__ float sW2e[H * H];   // Wm2 rows 16..31
    __shared__ float sWm2[H * H];   // Wm2 rows 0..15
    __shared__ float sWs2[H * H];   // Wsk2
    __shared__ float sb1[H], sb2[H], sbs2[H];
    __shared__ float sS[8][48];     // per warp: Sx[0:16) Se[16:32) h1[32:48)
    int tid = threadIdx.x;
    sW1e[tid] = Wm1[D_IN * H + tid];
    sWm2[tid] = Wm2[tid];
    sW2e[tid] = Wm2[H * H + tid];
    sWs2[tid] = Wsk2[tid];
    if (tid < H) { sb1[tid] = b1[tid]; sb2[tid] = b2[tid]; sbs2[tid] = bsk2[tid]; }
    __syncthreads();

    int w = tid >> 5, lane = tid & 31;
    int n = blockIdx.x * 8 + w;
    if (n >= N) return;
    int r1 = row_end(n);
    int r0 = (n == 0) ? 0 : row_end(n - 1);
    int eslot = lane >> 2, c = lane & 3;

    float ax0 = 0.f, ax1 = 0.f, ax2 = 0.f, ax3 = 0.f;
    float ae0 = 0.f, ae1 = 0.f, ae2 = 0.f, ae3 = 0.f;
    int p = r0 + eslot;
    while (p + 24 < r1) {
        int2 s0 = g_se[p];
        int2 s1 = g_se[p + 8];
        int2 s2 = g_se[p + 16];
        int2 s3 = g_se[p + 24];
        float4 e0 = __ldg((const float4*)ea + (size_t)s0.y * 4 + c);
        float4 e1 = __ldg((const float4*)ea + (size_t)s1.y * 4 + c);
        float4 e2 = __ldg((const float4*)ea + (size_t)s2.y * 4 + c);
        float4 e3 = __ldg((const float4*)ea + (size_t)s3.y * 4 + c);
        float4 x0 = __ldg((const float4*)g_xm + (size_t)s0.x * 4 + c);
        float4 x1 = __ldg((const float4*)g_xm + (size_t)s1.x * 4 + c);
        float4 x2 = __ldg((const float4*)g_xm + (size_t)s2.x * 4 + c);
        float4 x3 = __ldg((const float4*)g_xm + (size_t)s3.x * 4 + c);
        ax0 += (x0.x + x1.x) + (x2.x + x3.x);
        ax1 += (x0.y + x1.y) + (x2.y + x3.y);
        ax2 += (x0.z + x1.z) + (x2.z + x3.z);
        ax3 += (x0.w + x1.w) + (x2.w + x3.w);
        ae0 += (e0.x + e1.x) + (e2.x + e3.x);
        ae1 += (e0.y + e1.y) + (e2.y + e3.y);
        ae2 += (e0.z + e1.z) + (e2.z + e3.z);
        ae3 += (e0.w + e1.w) + (e2.w + e3.w);
        p += 32;
    }
    while (p < r1) {
        int2 se = g_se[p];
        float4 e4 = __ldg((const float4*)ea + (size_t)se.y * 4 + c);
        float4 x4 = __ldg((const float4*)g_xm + (size_t)se.x * 4 + c);
        ax0 += x4.x; ax1 += x4.y; ax2 += x4.z; ax3 += x4.w;
        ae0 += e4.x; ae1 += e4.y; ae2 += e4.z; ae3 += e4.w;
        p += 8;
    }
#pragma unroll
    for (int off = 4; off < 32; off <<= 1) {
        ax0 += __shfl_xor_sync(0xffffffffu, ax0, off);
        ax1 += __shfl_xor_sync(0xffffffffu, ax1, off);
        ax2 += __shfl_xor_sync(0xffffffffu, ax2, off);
        ax3 += __shfl_xor_sync(0xffffffffu, ax3, off);
        ae0 += __shfl_xor_sync(0xffffffffu, ae0, off);
        ae1 += __shfl_xor_sync(0xffffffffu, ae1, off);
        ae2 += __shfl_xor_sync(0xffffffffu, ae2, off);
        ae3 += __shfl_xor_sync(0xffffffffu, ae3, off);
    }
    if (eslot == 0) {
        float* S = sS[w];
        S[c * 4 + 0] = ax0; S[c * 4 + 1] = ax1; S[c * 4 + 2] = ax2; S[c * 4 + 3] = ax3;
        S[16 + c * 4 + 0] = ae0; S[16 + c * 4 + 1] = ae1; S[16 + c * 4 + 2] = ae2; S[16 + c * 4 + 3] = ae3;
    }
    __syncwarp();

    float deg = (float)(r1 - r0);
    if (lane < 16) {
        int j = lane;
        float a = sS[w][j] + deg * sb1[j] + g_sk1[n * H + j];
#pragma unroll
        for (int k = 0; k < H; k++) a = fmaf(sS[w][16 + k], sW1e[k * H + j], a);
        sS[w][32 + j] = fmaxf(a, 0.f);
    }
    __syncwarp();
    if (lane < 16) {
        int j = lane;
        float hm = 0.f;
        float a2 = deg * sb2[j] + sbs2[j];
#pragma unroll
        for (int k = 0; k < H; k++) {
            float hk = sS[w][32 + k];
            hm = fmaf(hk, sWm2[k * H + j], hm);
            a2 = fmaf(hk, sWs2[k * H + j], a2);
            a2 = fmaf(sS[w][16 + k], sW2e[k * H + j], a2);
        }
        g_hm[n * H + j] = hm;
        g_agg2[n * H + j] = a2;
    }
}

// ---------------------------------------------------------------------------
// pass_de (fused conv2-aggregate + lin3): one warp per node.
// ---------------------------------------------------------------------------
__global__ void __launch_bounds__(256, 6)
pass_de(const float* __restrict__ Wl3,
        const float* __restrict__ bl3,
        float* __restrict__ out, int N) {
    __shared__ float sW[H * D_IN];
    __shared__ float sb[D_IN];
    __shared__ float sH[8][20];
    int tid = threadIdx.x;
    for (int i = tid; i < H * D_IN; i += 256) sW[i] = Wl3[i];
    if (tid < D_IN) sb[tid] = bl3[tid];
    __syncthreads();

    int w = tid >> 5, lane = tid & 31;
    int n = blockIdx.x * 8 + w;
    if (n >= N) return;
    int r1 = row_end(n);
    int r0 = (n == 0) ? 0 : row_end(n - 1);
    int eslot = lane >> 2, c = lane & 3;

    float a0 = 0.f, a1 = 0.f, a2 = 0.f, a3 = 0.f;
    int p = r0 + eslot;
    while (p + 24 < r1) {
        int s0 = g_se[p].x;
        int s1 = g_se[p + 8].x;
        int s2 = g_se[p + 16].x;
        int s3 = g_se[p + 24].x;
        float4 h0 = __ldg((const float4*)g_hm + (size_t)s0 * 4 + c);
        float4 h1 = __ldg((const float4*)g_hm + (size_t)s1 * 4 + c);
        float4 h2 = __ldg((const float4*)g_hm + (size_t)s2 * 4 + c);
        float4 h3 = __ldg((const float4*)g_hm + (size_t)s3 * 4 + c);
        a0 += (h0.x + h1.x) + (h2.x + h3.x);
        a1 += (h0.y + h1.y) + (h2.y + h3.y);
        a2 += (h0.z + h1.z) + (h2.z + h3.z);
        a3 += (h0.w + h1.w) + (h2.w + h3.w);
        p += 32;
    }
    while (p < r1) {
        int src = g_se[p].x;
        float4 h4 = __ldg((const float4*)g_hm + (size_t)src * 4 + c);
        a0 += h4.x; a1 += h4.y; a2 += h4.z; a3 += h4.w;
        p += 8;
    }
#pragma unroll
    for (int off = 4; off < 32; off <<= 1) {
        a0 += __shfl_xor_sync(0xffffffffu, a0, off);
        a1 += __shfl_xor_sync(0xffffffffu, a1, off);
        a2 += __shfl_xor_sync(0xffffffffu, a2, off);
        a3 += __shfl_xor_sync(0xffffffffu, a3, off);
    }
    if (eslot == 0) {
        int b = c * 4;
        const float* ag = &g_agg2[n * H];
        sH[w][b + 0] = a0 + ag[b + 0];
        sH[w][b + 1] = a1 + ag[b + 1];
        sH[w][b + 2] = a2 + ag[b + 2];
        sH[w][b + 3] = a3 + ag[b + 3];
    }
    __syncwarp();

    float acc0 = sb[lane], acc1 = sb[lane + 32];
#pragma unroll
    for (int k = 0; k < H; k++) {
        float hk = sH[w][k];
        acc0 = fmaf(hk, sW[k * D_IN + lane], acc0);
        acc1 = fmaf(hk, sW[k * D_IN + lane + 32], acc1);
    }
    out[(size_t)n * D_IN + lane] = acc0;
    out[(size_t)n * D_IN + lane + 32] = acc1;
}

// ---------------------------------------------------------------------------
extern "C" void kernel_launch(void* const* d_in, const int* in_sizes, int n_in,
                              void* d_out, int out_size) {
    const float* x    = (const float*)d_in[0];
    const int*   ei   = (const int*)d_in[1];
    const float* ea   = (const float*)d_in[2];
    const float* Wm1  = (const float*)d_in[3];
    const float* bm1  = (const float*)d_in[4];
    const float* Wsk1 = (const float*)d_in[5];
    const float* bsk1 = (const float*)d_in[6];
    const float* Wm2  = (const float*)d_in[7];
    const float* bm2  = (const float*)d_in[8];
    const float* Wsk2 = (const float*)d_in[9];
    const float* bsk2 = (const float*)d_in[10];
    const float* Wl3  = (const float*)d_in[11];
    const float* bl3  = (const float*)d_in[12];
    float* out = (float*)d_out;

    int N = in_sizes[0] / D_IN;
    int E = in_sizes[1] / 2;

    int ebl = (E + HIST_EDGES - 1) / HIST_EDGES;
    int nsb = (N + 511) / 512;

    // lazily-created side stream + events for the pass_a fork (host-side only,
    // created once; reused identically every call -> deterministic work)
    static cudaStream_t s2 = nullptr;
    static cudaEvent_t ev_fork = nullptr, ev_join = nullptr;
    if (!s2) {
        cudaStreamCreateWithFlags(&s2, cudaStreamNonBlocking);
        cudaEventCreateWithFlags(&ev_fork, cudaEventDisableTiming);
        cudaEventCreateWithFlags(&ev_join, cudaEventDisableTiming);
    }

    void* cur_ptr = nullptr;
    void* done_ptr = nullptr;
    cudaGetSymbolAddress(&cur_ptr, g_cur);
    cudaGetSymbolAddress(&done_ptr, g_done);
    cudaMemsetAsync(cur_ptr, 0, (size_t)N * sizeof(int), 0);
    cudaMemsetAsync(done_ptr, 0, sizeof(int), 0);

    // fork: pass_a runs concurrently with hist/scan/scatter
    cudaEventRecord(ev_fork, 0);
    cudaStreamWaitEvent(s2, ev_fork, 0);
    pass_a<<<(N + 15) / 16, 256, 0, s2>>>(x, Wm1, Wsk1, bsk1, N);
    cudaEventRecord(ev_join, s2);

    k_hist<<<ebl, 256>>>(ei, E);
    k_scan<<<nsb, 512>>>(N);
    k_scatter<<<(E + 255) / 256, 256>>>(ei, E);

    // join before pass_bc (needs g_xm / g_sk1)
    cudaStreamWaitEvent(0, ev_join, 0);
    pass_bc<<<(N + 7) / 8, 256>>>(ea, Wm1, bm1, Wm2, bm2, Wsk2, bsk2, N);
    pass_de<<<(N + 7) / 8, 256>>>(Wl3, bl3, out, N);
}

// round 8
// speedup vs baseline: 1.0421x; 1.0104x over previous
#include <cuda_runtime.h>
#include <cstdint>

#define D_IN 64
#define D_EDGE 16
#define H 16
#define MAXN 102400
#define MAXE 3276800

// ---------------- static device scratch ----------------
__device__ float g_xm[MAXN * H + 64];    // x @ W_msg1[:64]
__device__ float g_sk1[MAXN * H + 64];   // x @ W_skip1 + b_skip1
__device__ float g_hm[MAXN * H + 64];    // h1 @ W_msg2[:16]
__device__ float g_agg2[MAXN * H + 64];  // conv2 partial (edge-const + skip2)
__device__ int   g_cur[MAXN];            // histogram -> local-exclusive prefix
__device__ int   g_bsum[512];            // scan block sums (exclusive)
__device__ int   g_done;                 // scan completion counter
__device__ int   g_rank[MAXE];           // within-dst rank (from hist atomic)
__device__ int2  g_se[MAXE];             // dst-sorted (src, eid)

// row start for node n (after scan): bsum[n>>9] + g_cur[n]  (global excl prefix)
__device__ __forceinline__ int row_start(int n) {
    return g_bsum[n >> 9] + g_cur[n];
}

#define HIST_EDGES 4096

// ---------------------------------------------------------------------------
// pass_a (side stream, overlaps hist/scan/scatter):
// per node: xm = x @ Wm1[:64], sk1 = x @ Wsk1 + b_sk1
// ---------------------------------------------------------------------------
__global__ void pass_a(const float* __restrict__ x,
                       const float* __restrict__ Wm1,
                       const float* __restrict__ Wsk1,
                       const float* __restrict__ bsk1,
                       int N) {
    __shared__ float sWm[D_IN * H];
    __shared__ float sWs[D_IN * H];
    __shared__ float sb[H];
    __shared__ float sx[16 * D_IN];
    int tid = threadIdx.x;
    for (int i = tid; i < D_IN * H; i += 256) { sWm[i] = Wm1[i]; sWs[i] = Wsk1[i]; }
    if (tid < H) sb[tid] = bsk1[tid];
    int nbase = blockIdx.x * 16;
    for (int i = tid; i < 16 * D_IN; i += 256) {
        int n = nbase + (i >> 6);
        sx[i] = (n < N) ? x[(size_t)n * D_IN + (i & 63)] : 0.f;
    }
    __syncthreads();
    int ln = tid >> 4, j = tid & 15;
    int n = nbase + ln;
    if (n >= N) return;
    const float* xr = &sx[ln * D_IN];
    float a = 0.f, s = sb[j];
#pragma unroll
    for (int k = 0; k < D_IN; k++) {
        float xv = xr[k];
        a = fmaf(xv, sWm[k * H + j], a);
        s = fmaf(xv, sWs[k * H + j], s);
    }
    int o = n * H + j;
    g_xm[o] = a;
    g_sk1[o] = s;
}

// ---------------------------------------------------------------------------
// k_hist: dst histogram; atomic return value IS the within-dst rank.
// ---------------------------------------------------------------------------
__global__ void k_hist(const int* __restrict__ ei, int E) {
    int base = blockIdx.x * HIST_EDGES;
    int lim = min(base + HIST_EDGES, E);
    for (int e = base + threadIdx.x; e < lim; e += 256) {
        int r = atomicAdd(&g_cur[ei[(size_t)E + e]], 1);
        g_rank[e] = r;
    }
}

// ---------------------------------------------------------------------------
// k_scan: fused two-level exclusive scan (last-block-done trick)
// ---------------------------------------------------------------------------
__global__ void k_scan(int N) {
    __shared__ int s[2][512];
    __shared__ int s_last;
    int t = threadIdx.x;
    int i = blockIdx.x * 512 + t;
    int v = (i < N) ? g_cur[i] : 0;
    s[0][t] = v;
    __syncthreads();
    int a = 0;
#pragma unroll
    for (int off = 1; off < 512; off <<= 1) {
        int sr = a; a ^= 1;
        s[a][t] = s[sr][t] + ((t >= off) ? s[sr][t - off] : 0);
        __syncthreads();
    }
    int incl = s[a][t];
    if (i < N) g_cur[i] = incl - v;  // local exclusive
    if (t == 511) g_bsum[blockIdx.x] = incl;
    __threadfence();
    __syncthreads();
    if (t == 0) s_last = (atomicAdd(&g_done, 1) == (int)gridDim.x - 1);
    __syncthreads();
    if (!s_last) return;
    int nsb = gridDim.x;
    int bv = (t < nsb) ? g_bsum[t] : 0;
    s[0][t] = bv;
    __syncthreads();
    a = 0;
#pragma unroll
    for (int off = 1; off < 512; off <<= 1) {
        int sr = a; a ^= 1;
        s[a][t] = s[sr][t] + ((t >= off) ? s[sr][t - off] : 0);
        __syncthreads();
    }
    if (t < nsb) g_bsum[t] = s[a][t] - bv;
}

// ---------------------------------------------------------------------------
// k_scatter: atomic-FREE scatter using precomputed ranks
// ---------------------------------------------------------------------------
__global__ void k_scatter(const int* __restrict__ ei, int E) {
    int e = blockIdx.x * 256 + threadIdx.x;
    if (e >= E) return;
    int s = ei[e];
    int d = ei[(size_t)E + e];
    int p = g_bsum[d >> 9] + g_cur[d] + g_rank[e];
    g_se[p] = make_int2(s, e);
}

// ---------------------------------------------------------------------------
// pass_bc (fused conv1 + inter-layer): one warp per node.
// lanes: eslot = lane>>2 (8 parallel edges), c = lane&3 (f4 quarter)
// ---------------------------------------------------------------------------
__global__ void __launch_bounds__(256, 6)
pass_bc(const float* __restrict__ ea,
        const float* __restrict__ Wm1,
        const float* __restrict__ b1,
        const float* __restrict__ Wm2,
        const float* __restrict__ b2,
        const float* __restrict__ Wsk2,
        const float* __restrict__ bsk2,
        int N, int E) {
    __shared__ float sW1e[H * H];   // Wm1 rows 64..79
    __shared__ float sW2e[H * H];   // Wm2 rows 16..31
    __shared__ float sWm2[H * H];   // Wm2 rows 0..15
    __shared__ float sWs2[H * H];   // Wsk2
    __shared__ float sb1[H], sb2[H], sbs2[H];
    __shared__ float sS[8][48];     // per warp: Sx[0:16) Se[16:32) h1[32:48)
    int tid = threadIdx.x;
    sW1e[tid] = Wm1[D_IN * H + tid];
    sWm2[tid] = Wm2[tid];
    sW2e[tid] = Wm2[H * H + tid];
    sWs2[tid] = Wsk2[tid];
    if (tid < H) { sb1[tid] = b1[tid]; sb2[tid] = b2[tid]; sbs2[tid] = bsk2[tid]; }
    __syncthreads();

    int w = tid >> 5, lane = tid & 31;
    int n = blockIdx.x * 8 + w;
    if (n >= N) return;
    int r0 = row_start(n);
    int r1 = (n + 1 < N) ? row_start(n + 1) : E;
    int eslot = lane >> 2, c = lane & 3;

    float ax0 = 0.f, ax1 = 0.f, ax2 = 0.f, ax3 = 0.f;
    float ae0 = 0.f, ae1 = 0.f, ae2 = 0.f, ae3 = 0.f;
    int p = r0 + eslot;
    while (p + 24 < r1) {
        int2 s0 = g_se[p];
        int2 s1 = g_se[p + 8];
        int2 s2 = g_se[p + 16];
        int2 s3 = g_se[p + 24];
        float4 e0 = __ldcs((const float4*)ea + (size_t)s0.y * 4 + c);
        float4 e1 = __ldcs((const float4*)ea + (size_t)s1.y * 4 + c);
        float4 e2 = __ldcs((const float4*)ea + (size_t)s2.y * 4 + c);
        float4 e3 = __ldcs((const float4*)ea + (size_t)s3.y * 4 + c);
        float4 x0 = __ldg((const float4*)g_xm + (size_t)s0.x * 4 + c);
        float4 x1 = __ldg((const float4*)g_xm + (size_t)s1.x * 4 + c);
        float4 x2 = __ldg((const float4*)g_xm + (size_t)s2.x * 4 + c);
        float4 x3 = __ldg((const float4*)g_xm + (size_t)s3.x * 4 + c);
        ax0 += (x0.x + x1.x) + (x2.x + x3.x);
        ax1 += (x0.y + x1.y) + (x2.y + x3.y);
        ax2 += (x0.z + x1.z) + (x2.z + x3.z);
        ax3 += (x0.w + x1.w) + (x2.w + x3.w);
        ae0 += (e0.x + e1.x) + (e2.x + e3.x);
        ae1 += (e0.y + e1.y) + (e2.y + e3.y);
        ae2 += (e0.z + e1.z) + (e2.z + e3.z);
        ae3 += (e0.w + e1.w) + (e2.w + e3.w);
        p += 32;
    }
    while (p < r1) {
        int2 se = g_se[p];
        float4 e4 = __ldcs((const float4*)ea + (size_t)se.y * 4 + c);
        float4 x4 = __ldg((const float4*)g_xm + (size_t)se.x * 4 + c);
        ax0 += x4.x; ax1 += x4.y; ax2 += x4.z; ax3 += x4.w;
        ae0 += e4.x; ae1 += e4.y; ae2 += e4.z; ae3 += e4.w;
        p += 8;
    }
#pragma unroll
    for (int off = 4; off < 32; off <<= 1) {
        ax0 += __shfl_xor_sync(0xffffffffu, ax0, off);
        ax1 += __shfl_xor_sync(0xffffffffu, ax1, off);
        ax2 += __shfl_xor_sync(0xffffffffu, ax2, off);
        ax3 += __shfl_xor_sync(0xffffffffu, ax3, off);
        ae0 += __shfl_xor_sync(0xffffffffu, ae0, off);
        ae1 += __shfl_xor_sync(0xffffffffu, ae1, off);
        ae2 += __shfl_xor_sync(0xffffffffu, ae2, off);
        ae3 += __shfl_xor_sync(0xffffffffu, ae3, off);
    }
    if (eslot == 0) {
        float* S = sS[w];
        S[c * 4 + 0] = ax0; S[c * 4 + 1] = ax1; S[c * 4 + 2] = ax2; S[c * 4 + 3] = ax3;
        S[16 + c * 4 + 0] = ae0; S[16 + c * 4 + 1] = ae1; S[16 + c * 4 + 2] = ae2; S[16 + c * 4 + 3] = ae3;
    }
    __syncwarp();

    float deg = (float)(r1 - r0);
    if (lane < 16) {
        int j = lane;
        float a = sS[w][j] + deg * sb1[j] + g_sk1[n * H + j];
#pragma unroll
        for (int k = 0; k < H; k++) a = fmaf(sS[w][16 + k], sW1e[k * H + j], a);
        sS[w][32 + j] = fmaxf(a, 0.f);
    }
    __syncwarp();
    if (lane < 16) {
        int j = lane;
        float hm = 0.f;
        float a2 = deg * sb2[j] + sbs2[j];
#pragma unroll
        for (int k = 0; k < H; k++) {
            float hk = sS[w][32 + k];
            hm = fmaf(hk, sWm2[k * H + j], hm);
            a2 = fmaf(hk, sWs2[k * H + j], a2);
            a2 = fmaf(sS[w][16 + k], sW2e[k * H + j], a2);
        }
        g_hm[n * H + j] = hm;
        g_agg2[n * H + j] = a2;
    }
}

// ---------------------------------------------------------------------------
// pass_de (fused conv2-aggregate + lin3): one warp per node.
// ---------------------------------------------------------------------------
__global__ void __launch_bounds__(256, 6)
pass_de(const float* __restrict__ Wl3,
        const float* __restrict__ bl3,
        float* __restrict__ out, int N, int E) {
    __shared__ float sW[H * D_IN];
    __shared__ float sb[D_IN];
    __shared__ float sH[8][20];
    int tid = threadIdx.x;
    for (int i = tid; i < H * D_IN; i += 256) sW[i] = Wl3[i];
    if (tid < D_IN) sb[tid] = bl3[tid];
    __syncthreads();

    int w = tid >> 5, lane = tid & 31;
    int n = blockIdx.x * 8 + w;
    if (n >= N) return;
    int r0 = row_start(n);
    int r1 = (n + 1 < N) ? row_start(n + 1) : E;
    int eslot = lane >> 2, c = lane & 3;

    float a0 = 0.f, a1 = 0.f, a2 = 0.f, a3 = 0.f;
    int p = r0 + eslot;
    while (p + 24 < r1) {
        int s0 = g_se[p].x;
        int s1 = g_se[p + 8].x;
        int s2 = g_se[p + 16].x;
        int s3 = g_se[p + 24].x;
        float4 h0 = __ldg((const float4*)g_hm + (size_t)s0 * 4 + c);
        float4 h1 = __ldg((const float4*)g_hm + (size_t)s1 * 4 + c);
        float4 h2 = __ldg((const float4*)g_hm + (size_t)s2 * 4 + c);
        float4 h3 = __ldg((const float4*)g_hm + (size_t)s3 * 4 + c);
        a0 += (h0.x + h1.x) + (h2.x + h3.x);
        a1 += (h0.y + h1.y) + (h2.y + h3.y);
        a2 += (h0.z + h1.z) + (h2.z + h3.z);
        a3 += (h0.w + h1.w) + (h2.w + h3.w);
        p += 32;
    }
    while (p < r1) {
        int src = g_se[p].x;
        float4 h4 = __ldg((const float4*)g_hm + (size_t)src * 4 + c);
        a0 += h4.x; a1 += h4.y; a2 += h4.z; a3 += h4.w;
        p += 8;
    }
#pragma unroll
    for (int off = 4; off < 32; off <<= 1) {
        a0 += __shfl_xor_sync(0xffffffffu, a0, off);
        a1 += __shfl_xor_sync(0xffffffffu, a1, off);
        a2 += __shfl_xor_sync(0xffffffffu, a2, off);
        a3 += __shfl_xor_sync(0xffffffffu, a3, off);
    }
    if (eslot == 0) {
        int b = c * 4;
        const float* ag = &g_agg2[n * H];
        sH[w][b + 0] = a0 + ag[b + 0];
        sH[w][b + 1] = a1 + ag[b + 1];
        sH[w][b + 2] = a2 + ag[b + 2];
        sH[w][b + 3] = a3 + ag[b + 3];
    }
    __syncwarp();

    float acc0 = sb[lane], acc1 = sb[lane + 32];
#pragma unroll
    for (int k = 0; k < H; k++) {
        float hk = sH[w][k];
        acc0 = fmaf(hk, sW[k * D_IN + lane], acc0);
        acc1 = fmaf(hk, sW[k * D_IN + lane + 32], acc1);
    }
    out[(size_t)n * D_IN + lane] = acc0;
    out[(size_t)n * D_IN + lane + 32] = acc1;
}

// ---------------------------------------------------------------------------
extern "C" void kernel_launch(void* const* d_in, const int* in_sizes, int n_in,
                              void* d_out, int out_size) {
    const float* x    = (const float*)d_in[0];
    const int*   ei   = (const int*)d_in[1];
    const float* ea   = (const float*)d_in[2];
    const float* Wm1  = (const float*)d_in[3];
    const float* bm1  = (const float*)d_in[4];
    const float* Wsk1 = (const float*)d_in[5];
    const float* bsk1 = (const float*)d_in[6];
    const float* Wm2  = (const float*)d_in[7];
    const float* bm2  = (const float*)d_in[8];
    const float* Wsk2 = (const float*)d_in[9];
    const float* bsk2 = (const float*)d_in[10];
    const float* Wl3  = (const float*)d_in[11];
    const float* bl3  = (const float*)d_in[12];
    float* out = (float*)d_out;

    int N = in_sizes[0] / D_IN;
    int E = in_sizes[1] / 2;

    int ebl = (E + HIST_EDGES - 1) / HIST_EDGES;
    int nsb = (N + 511) / 512;

    static cudaStream_t s2 = nullptr;
    static cudaEvent_t ev_fork = nullptr, ev_join = nullptr;
    if (!s2) {
        cudaStreamCreateWithFlags(&s2, cudaStreamNonBlocking);
        cudaEventCreateWithFlags(&ev_fork, cudaEventDisableTiming);
        cudaEventCreateWithFlags(&ev_join, cudaEventDisableTiming);
    }

    void* cur_ptr = nullptr;
    void* done_ptr = nullptr;
    cudaGetSymbolAddress(&cur_ptr, g_cur);
    cudaGetSymbolAddress(&done_ptr, g_done);
    cudaMemsetAsync(cur_ptr, 0, (size_t)N * sizeof(int), 0);
    cudaMemsetAsync(done_ptr, 0, sizeof(int), 0);

    // fork: pass_a runs concurrently with hist/scan/scatter
    cudaEventRecord(ev_fork, 0);
    cudaStreamWaitEvent(s2, ev_fork, 0);
    pass_a<<<(N + 15) / 16, 256, 0, s2>>>(x, Wm1, Wsk1, bsk1, N);
    cudaEventRecord(ev_join, s2);

    k_hist<<<ebl, 256>>>(ei, E);
    k_scan<<<nsb, 512>>>(N);
    k_scatter<<<(E + 255) / 256, 256>>>(ei, E);

    cudaStreamWaitEvent(0, ev_join, 0);
    pass_bc<<<(N + 7) / 8, 256>>>(ea, Wm1, bm1, Wm2, bm2, Wsk2, bsk2, N, E);
    pass_de<<<(N + 7) / 8, 256>>>(Wl3, bl3, out, N, E);
}